// round 14
// baseline (speedup 1.0000x reference)
#include <cuda_runtime.h>
#include <cuda_bf16.h>
#include <math.h>
#include <stdint.h>

#define BB 64
#define SS 512
#define HH 1024
#define TT 24
#define NROWS (BB*SS)

#define GRID 148
#define NTH 512                    // 16 warps
#define NWARP 16
#define NCHUNK 64                  // K chunks of 16
#define NTILES (NROWS/16)          // 2048 tiles of 16 rows
#define RING 10                    // cp.async ring stages per warp
#define STAGE_BYTES 1024           // 16 rows x 64 B
#define SMEM_TOTAL (NWARP*RING*STAGE_BYTES)   // 163840

// ---------------- device scratch ----------------
__device__ float    g_loss_sum;
__device__ unsigned g_ticket;
__device__ unsigned g_tile;
// pre-packed B fragments: [nt][chunk][lane] = {bh0,bh1,bl0,bl1}  (98304 B, L1-resident)
__device__ uint4    g_wfrag[3 * NCHUNK * 32];

__device__ __forceinline__ float neg_inf() { return __int_as_float(0xff800000); }

__device__ __forceinline__ uint32_t packbf(float x, float y) {
    uint32_t r; asm("cvt.rn.bf16x2.f32 %0, %1, %2;" : "=r"(r) : "f"(y), "f"(x)); return r;
}
__device__ __forceinline__ void split2f(float x, float y, uint32_t& hi, uint32_t& lo) {
    hi = packbf(x, y);
    float rx = x - __uint_as_float(hi << 16);
    float ry = y - __uint_as_float(hi & 0xFFFF0000u);
    lo = packbf(rx, ry);
}

__device__ __forceinline__ void mma16816(float* c, const uint32_t* a, uint32_t b0, uint32_t b1) {
    asm volatile("mma.sync.aligned.m16n8k16.row.col.f32.bf16.bf16.f32 "
        "{%0,%1,%2,%3}, {%4,%5,%6,%7}, {%8,%9}, {%0,%1,%2,%3};"
        : "+f"(c[0]), "+f"(c[1]), "+f"(c[2]), "+f"(c[3])
        : "r"(a[0]), "r"(a[1]), "r"(a[2]), "r"(a[3]), "r"(b0), "r"(b1));
}

__device__ __forceinline__ void cp_async16(unsigned s, const void* g) {
    asm volatile("cp.async.cg.shared.global [%0], [%1], 16;" :: "r"(s), "l"(g));
}
#define CP_COMMIT() asm volatile("cp.async.commit_group;")
#define CP_WAIT8()  asm volatile("cp.async.wait_group 8;")

__device__ __forceinline__ int getmask(const void* p, int mt, long i) {
    return mt == 0 ? (((const unsigned char*)p)[i] != 0)
         : mt == 1 ? (((const float*)p)[i] != 0.0f)
                   : (((const int*)p)[i] != 0);
}

// ================= prep: pack W into HMMA B-fragment layout =================
__global__ void prep_kernel(const float* __restrict__ W) {
    const int idx = blockIdx.x * blockDim.x + threadIdx.x;   // 0 .. 6143
    const int nt = idx / (NCHUNK * 32);
    const int rem = idx % (NCHUNK * 32);
    const int c = rem >> 5, lane = rem & 31;
    const int n = nt * 8 + (lane >> 2), kp = lane & 3;
    const float* wr = W + n * HH + c * 16 + kp * 4;
    uint4 f;
    uint32_t lo;
    split2f(wr[0], wr[1], f.x, lo); f.z = lo;
    split2f(wr[2], wr[3], f.y, lo); f.w = lo;
    g_wfrag[idx] = f;
}

// ================= single fused persistent kernel =================
__global__ void __launch_bounds__(NTH, 1)
crf_kernel(const float* __restrict__ feats, const float* __restrict__ W,
           const float* __restrict__ bias, const int* __restrict__ target,
           const void* __restrict__ mask_raw, const float* __restrict__ trans,
           float* __restrict__ out, int has_loss) {
    extern __shared__ unsigned char smem[];
    __shared__ float sred[NWARP];
    __shared__ float st[TT * TT];       // generic path only
    __shared__ float sp[NWARP * TT];    // generic path only
    __shared__ int   s_flag, s_nz;
    __shared__ float s_tot;

    const int tid = threadIdx.x, warp = tid >> 5, lane = tid & 31;
    const int r = lane >> 2, kp = lane & 3;
    float* emis = out + has_loss;       // 4B-aligned only: scalar stores

    if (tid < NWARP) sred[tid] = 0.0f;
    if (tid == 0) { s_flag = 0; s_nz = 0; s_tot = 0.0f; }
    __syncthreads();

    const unsigned u0 = *(const unsigned*)mask_raw;
    const int mt_ = (u0 == 0x01010101u) ? 0 : ((u0 == 0x3F800000u) ? 1 : 2);

    const float4* f4g = (const float4*)feats;
    const uint4* wf_base = g_wfrag + lane;
    unsigned ring32;
    {
        unsigned char* rb = smem + warp * (RING * STAGE_BYTES);
        asm("{ .reg .u64 t; cvta.to.shared.u64 t, %1; cvt.u32.u64 %0, t; }"
            : "=r"(ring32) : "l"(rb));
    }
    float contrib = 0.0f;

    // ---- per-warp 16-row tile steal loop ----
    for (;;) {
        unsigned tile;
        if (lane == 0) tile = atomicAdd(&g_tile, 1u);
        tile = __shfl_sync(0xffffffffu, tile, 0);
        if (tile >= NTILES) break;
        const long row0 = (long)tile * 16;

        const long ra = (row0 + r)     * 256 + kp;   // float4 units
        const long rb = (row0 + r + 8) * 256 + kp;

        float acc[3][4];
        #pragma unroll
        for (int nt = 0; nt < 3; nt++)
            #pragma unroll
            for (int q = 0; q < 4; q++) acc[nt][q] = 0.0f;

        // prologue: stage chunks 0..8 (one commit group each)
        #pragma unroll
        for (int p = 0; p < RING - 1; p++) {
            unsigned sdst = ring32 + (unsigned)p * STAGE_BYTES;
            cp_async16(sdst + (unsigned)lane * 16,        f4g + ra + p * 4);
            cp_async16(sdst + (unsigned)(lane + 32) * 16, f4g + rb + p * 4);
            CP_COMMIT();
        }

        #pragma unroll 4
        for (int c = 0; c < NCHUNK; c++) {
            CP_WAIT8();   // own chunk-c group complete (identity thread mapping)
            const int slot = c % RING;
            const unsigned scur = ring32 + (unsigned)slot * STAGE_BYTES;
            float4 a0, a1;
            asm volatile("ld.shared.v4.f32 {%0,%1,%2,%3}, [%4];"
                : "=f"(a0.x), "=f"(a0.y), "=f"(a0.z), "=f"(a0.w)
                : "r"(scur + (unsigned)lane * 16));
            asm volatile("ld.shared.v4.f32 {%0,%1,%2,%3}, [%4];"
                : "=f"(a1.x), "=f"(a1.y), "=f"(a1.z), "=f"(a1.w)
                : "r"(scur + (unsigned)(lane + 32) * 16));

            if (c + RING - 1 < NCHUNK) {
                const int nc = c + RING - 1;
                unsigned sdst = ring32 + (unsigned)(nc % RING) * STAGE_BYTES;
                cp_async16(sdst + (unsigned)lane * 16,        f4g + ra + nc * 4);
                cp_async16(sdst + (unsigned)(lane + 32) * 16, f4g + rb + nc * 4);
            }
            CP_COMMIT();   // every iteration: uniform group counting

            uint4 w0 = __ldg(wf_base + c * 32);
            uint4 w1 = __ldg(wf_base + (NCHUNK * 32) + c * 32);
            uint4 w2 = __ldg(wf_base + (2 * NCHUNK * 32) + c * 32);

            uint32_t ahi[4], alo[4];
            split2f(a0.x, a0.y, ahi[0], alo[0]);
            split2f(a1.x, a1.y, ahi[1], alo[1]);
            split2f(a0.z, a0.w, ahi[2], alo[2]);
            split2f(a1.z, a1.w, ahi[3], alo[3]);

            mma16816(acc[0], ahi, w0.x, w0.y);
            mma16816(acc[0], ahi, w0.z, w0.w);
            mma16816(acc[0], alo, w0.x, w0.y);
            mma16816(acc[1], ahi, w1.x, w1.y);
            mma16816(acc[1], ahi, w1.z, w1.w);
            mma16816(acc[1], alo, w1.x, w1.y);
            mma16816(acc[2], ahi, w2.x, w2.y);
            mma16816(acc[2], ahi, w2.z, w2.w);
            mma16816(acc[2], alo, w2.x, w2.y);
        }

        // ---- epilogue: bias, scalar emission stores, quad-shfl LSE + target ----
        #pragma unroll
        for (int rr = 0; rr < 2; rr++) {
            const long row = row0 + rr * 8 + r;
            float e[6];
            float* eo = emis + row * TT;
            #pragma unroll
            for (int nt = 0; nt < 3; nt++) {
                const int col = nt * 8 + kp * 2;
                e[nt * 2]     = acc[nt][rr * 2]     + __ldg(bias + col);
                e[nt * 2 + 1] = acc[nt][rr * 2 + 1] + __ldg(bias + col + 1);
                eo[col]     = e[nt * 2];
                eo[col + 1] = e[nt * 2 + 1];
            }
            float mx = e[0];
            #pragma unroll
            for (int q = 1; q < 6; q++) mx = fmaxf(mx, e[q]);
            mx = fmaxf(mx, __shfl_xor_sync(0xffffffffu, mx, 1));
            mx = fmaxf(mx, __shfl_xor_sync(0xffffffffu, mx, 2));
            float ex = 0.0f;
            #pragma unroll
            for (int q = 0; q < 6; q++) ex += __expf(e[q] - mx);
            const int tg = target[row];
            float sc = 0.0f;
            #pragma unroll
            for (int nt = 0; nt < 3; nt++) {
                const int col = nt * 8 + kp * 2;
                sc += (tg == col) ? e[nt * 2] : 0.0f;
                sc += (tg == col + 1) ? e[nt * 2 + 1] : 0.0f;
            }
            ex += __shfl_xor_sync(0xffffffffu, ex, 1);
            sc += __shfl_xor_sync(0xffffffffu, sc, 1);
            ex += __shfl_xor_sync(0xffffffffu, ex, 2);
            sc += __shfl_xor_sync(0xffffffffu, sc, 2);
            if (kp == 0) {
                const float lse = mx + __logf(ex);
                const int s  = (int)(row & (SS - 1));
                const int mk = getmask(mask_raw, mt_, row);
                contrib += mk ? (sc - lse) : (s == 0 ? -lse : 0.0f);
            }
        }
    }

    // ---- warp + block reduce, ticket ----
    contrib += __shfl_xor_sync(0xffffffffu, contrib, 16);
    contrib += __shfl_xor_sync(0xffffffffu, contrib, 8);
    contrib += __shfl_xor_sync(0xffffffffu, contrib, 4);
    contrib += __shfl_xor_sync(0xffffffffu, contrib, 2);
    contrib += __shfl_xor_sync(0xffffffffu, contrib, 1);
    if (lane == 0) sred[warp] = contrib;
    __syncthreads();
    if (tid == 0) {
        float part = 0.0f;
        #pragma unroll
        for (int w = 0; w < NWARP; w++) part += sred[w];
        atomicAdd(&g_loss_sum, part);
        __threadfence();
        unsigned tk = atomicAdd(&g_ticket, 1u);
        s_flag = (tk == GRID - 1);
    }
    __syncthreads();
    if (!s_flag) return;

    // ================= last block: finalize =================
    {
        int lnz = 0;
        for (int i = tid; i < TT * TT; i += NTH) {
            float v = trans[i];
            st[i] = v;
            lnz |= (v != 0.0f);
        }
        if (lnz) atomicOr(&s_nz, 1);
    }
    __syncthreads();

    if (!s_nz) {
        if (tid == 0) {
            if (has_loss) out[0] = -g_loss_sum / (float)BB;
            g_loss_sum = 0.0f;
            g_ticket = 0u;
            g_tile = 0u;
        }
        return;
    }

    // generic nonzero-transition path (not taken for this dataset)
    {
        float wsum = 0.0f;
        float* msp = sp + warp * TT;
        for (int b = warp; b < BB; b += NWARP) {
            float sum = 0.0f;
            for (int s = lane; s < SS; s += 32) {
                const long idx = (long)b * SS + s;
                if (getmask(mask_raw, mt_, idx)) {
                    float v = emis[idx * TT + target[idx]];
                    if (s > 0) v += st[target[idx - 1] * TT + target[idx]];
                    sum += v;
                }
            }
            sum += __shfl_xor_sync(0xffffffffu, sum, 16);
            sum += __shfl_xor_sync(0xffffffffu, sum, 8);
            sum += __shfl_xor_sync(0xffffffffu, sum, 4);
            sum += __shfl_xor_sync(0xffffffffu, sum, 2);
            sum += __shfl_xor_sync(0xffffffffu, sum, 1);

            if (lane < TT) msp[lane] = emis[(long)b * SS * TT + lane];
            __syncwarp();
            for (int s = 1; s < SS; s++) {
                if (getmask(mask_raw, mt_, (long)b * SS + s)) {
                    float nv = 0.0f;
                    if (lane < TT) {
                        float mm = neg_inf();
                        #pragma unroll
                        for (int j = 0; j < TT; j++) mm = fmaxf(mm, msp[j] + st[j * TT + lane]);
                        float a = 0.0f;
                        #pragma unroll
                        for (int j = 0; j < TT; j++) a += __expf(msp[j] + st[j * TT + lane] - mm);
                        nv = emis[((long)b * SS + s) * TT + lane] + mm + __logf(a);
                    }
                    __syncwarp();
                    if (lane < TT) msp[lane] = nv;
                    __syncwarp();
                }
            }
            float e2 = (lane < TT) ? msp[lane] : neg_inf();
            float mm = e2;
            mm = fmaxf(mm, __shfl_xor_sync(0xffffffffu, mm, 16));
            mm = fmaxf(mm, __shfl_xor_sync(0xffffffffu, mm, 8));
            mm = fmaxf(mm, __shfl_xor_sync(0xffffffffu, mm, 4));
            mm = fmaxf(mm, __shfl_xor_sync(0xffffffffu, mm, 2));
            mm = fmaxf(mm, __shfl_xor_sync(0xffffffffu, mm, 1));
            float ex2 = (lane < TT) ? __expf(e2 - mm) : 0.0f;
            ex2 += __shfl_xor_sync(0xffffffffu, ex2, 16);
            ex2 += __shfl_xor_sync(0xffffffffu, ex2, 8);
            ex2 += __shfl_xor_sync(0xffffffffu, ex2, 4);
            ex2 += __shfl_xor_sync(0xffffffffu, ex2, 2);
            ex2 += __shfl_xor_sync(0xffffffffu, ex2, 1);
            if (lane == 0) wsum += sum - (mm + __logf(ex2));
        }
        if (lane == 0) atomicAdd(&s_tot, wsum);
    }
    __syncthreads();
    if (tid == 0) {
        if (has_loss) out[0] = -s_tot / (float)BB;
        g_loss_sum = 0.0f;
        g_ticket = 0u;
        g_tile = 0u;
    }
}

// ---------------- launch ----------------
extern "C" void kernel_launch(void* const* d_in, const int* in_sizes, int n_in,
                              void* d_out, int out_size) {
    const float* feats  = (const float*)d_in[0];   // (B,S,H)
    const int*   target = (const int*)d_in[1];     // (B,S)
    const void*  mask   = d_in[2];                 // (B,S) dtype auto-detected
    const float* W      = (const float*)d_in[3];   // (T,H)
    const float* bias   = (const float*)d_in[4];   // (T,)
    const float* trans  = (const float*)d_in[5];   // (T,T)

    float* out = (float*)d_out;
    const int has_loss = (out_size == NROWS * TT + 1) ? 1 : 0;

    static int attr_set = 0;
    if (!attr_set) {
        cudaFuncSetAttribute(crf_kernel, cudaFuncAttributeMaxDynamicSharedMemorySize, SMEM_TOTAL);
        attr_set = 1;
    }

    prep_kernel<<<24, 256>>>(W);
    crf_kernel<<<GRID, NTH, SMEM_TOTAL>>>(feats, W, bias, target, mask, trans, out, has_loss);
}

// round 15
// speedup vs baseline: 1.4362x; 1.4362x over previous
#include <cuda_runtime.h>
#include <cuda_bf16.h>
#include <math.h>
#include <stdint.h>

#define BB 64
#define SS 512
#define HH 1024
#define TT 24
#define NROWS (BB*SS)

#define GRID 148
#define NTH 448                    // 14 warps -> 146 regs/thread budget
#define NWARP 14
#define NCHUNK 64                  // K chunks of 16
#define NTILES (NROWS/16)          // 2048 tiles of 16 rows (<= 148*14 = 2072 warps)

// ---------------- device scratch ----------------
__device__ float    g_loss_sum;
__device__ unsigned g_ticket;
// pre-packed B fragments: [nt][chunk][lane] = {bh0,bh1,bl0,bl1}  (98304 B, L1-resident)
__device__ uint4    g_wfrag[3 * NCHUNK * 32];

__device__ __forceinline__ float neg_inf() { return __int_as_float(0xff800000); }

__device__ __forceinline__ uint32_t packbf(float x, float y) {
    uint32_t r; asm("cvt.rn.bf16x2.f32 %0, %1, %2;" : "=r"(r) : "f"(y), "f"(x)); return r;
}
__device__ __forceinline__ void split2f(float x, float y, uint32_t& hi, uint32_t& lo) {
    hi = packbf(x, y);
    float rx = x - __uint_as_float(hi << 16);
    float ry = y - __uint_as_float(hi & 0xFFFF0000u);
    lo = packbf(rx, ry);
}

__device__ __forceinline__ void mma16816(float* c, const uint32_t* a, uint32_t b0, uint32_t b1) {
    asm volatile("mma.sync.aligned.m16n8k16.row.col.f32.bf16.bf16.f32 "
        "{%0,%1,%2,%3}, {%4,%5,%6,%7}, {%8,%9}, {%0,%1,%2,%3};"
        : "+f"(c[0]), "+f"(c[1]), "+f"(c[2]), "+f"(c[3])
        : "r"(a[0]), "r"(a[1]), "r"(a[2]), "r"(a[3]), "r"(b0), "r"(b1));
}

__device__ __forceinline__ int getmask(const void* p, int mt, long i) {
    return mt == 0 ? (((const unsigned char*)p)[i] != 0)
         : mt == 1 ? (((const float*)p)[i] != 0.0f)
                   : (((const int*)p)[i] != 0);
}

// ================= prep: pack W into HMMA B-fragment layout =================
__global__ void prep_kernel(const float* __restrict__ W) {
    const int idx = blockIdx.x * blockDim.x + threadIdx.x;   // 0 .. 6143
    const int nt = idx / (NCHUNK * 32);
    const int rem = idx % (NCHUNK * 32);
    const int c = rem >> 5, lane = rem & 31;
    const int n = nt * 8 + (lane >> 2), kp = lane & 3;
    const float* wr = W + n * HH + c * 16 + kp * 4;
    uint4 f;
    uint32_t lo;
    split2f(wr[0], wr[1], f.x, lo); f.z = lo;
    split2f(wr[2], wr[3], f.y, lo); f.w = lo;
    g_wfrag[idx] = f;
}

// ================= single fused kernel =================
__global__ void __launch_bounds__(NTH, 1)
crf_kernel(const float* __restrict__ feats, const float* __restrict__ W,
           const float* __restrict__ bias, const int* __restrict__ target,
           const void* __restrict__ mask_raw, const float* __restrict__ trans,
           float* __restrict__ out, int has_loss) {
    __shared__ float sred[NWARP];
    __shared__ float st[TT * TT];       // generic path only
    __shared__ float sp[NWARP * TT];    // generic path only
    __shared__ int   s_flag, s_nz;
    __shared__ float s_tot;

    const int tid = threadIdx.x, warp = tid >> 5, lane = tid & 31;
    const int r = lane >> 2, kp = lane & 3;
    float* emis = out + has_loss;       // 4B-aligned only: scalar stores

    if (tid < NWARP) sred[tid] = 0.0f;
    if (tid == 0) { s_flag = 0; s_nz = 0; s_tot = 0.0f; }
    __syncthreads();

    const unsigned u0 = *(const unsigned*)mask_raw;
    const int mt_ = (u0 == 0x01010101u) ? 0 : ((u0 == 0x3F800000u) ? 1 : 2);

    const float4* f4g = (const float4*)feats;
    const uint4* wf_base = g_wfrag + lane;
    float contrib = 0.0f;

    // ---- static tile: one 16-row tile per warp ----
    const int tile = blockIdx.x * NWARP + warp;
    if (tile < NTILES) {
        const long row0 = (long)tile * 16;
        const long ra = (row0 + r)     * 256 + kp;   // float4 units
        const long rb = (row0 + r + 8) * 256 + kp;

        float acc[3][4];
        #pragma unroll
        for (int nt = 0; nt < 3; nt++)
            #pragma unroll
            for (int q = 0; q < 4; q++) acc[nt][q] = 0.0f;

        // 8-buffer rotation, prefetch distance 7
        float4 fb0[2], fb1[2], fb2[2], fb3[2], fb4[2], fb5[2], fb6[2], fb7[2];

        #define LOADC(buf, c) do { \
            int _nc = (c) < NCHUNK ? (c) : (NCHUNK - 1); \
            buf[0] = __ldcs(f4g + ra + _nc * 4); \
            buf[1] = __ldcs(f4g + rb + _nc * 4); \
        } while (0)

        #define COMPUTE(buf, ch) do { \
            uint4 w0 = __ldg(wf_base + (ch) * 32); \
            uint4 w1 = __ldg(wf_base + (NCHUNK * 32) + (ch) * 32); \
            uint4 w2 = __ldg(wf_base + (2 * NCHUNK * 32) + (ch) * 32); \
            uint32_t ahi[4], alo[4]; \
            split2f(buf[0].x, buf[0].y, ahi[0], alo[0]); \
            split2f(buf[1].x, buf[1].y, ahi[1], alo[1]); \
            split2f(buf[0].z, buf[0].w, ahi[2], alo[2]); \
            split2f(buf[1].z, buf[1].w, ahi[3], alo[3]); \
            mma16816(acc[0], ahi, w0.x, w0.y); \
            mma16816(acc[0], ahi, w0.z, w0.w); \
            mma16816(acc[0], alo, w0.x, w0.y); \
            mma16816(acc[1], ahi, w1.x, w1.y); \
            mma16816(acc[1], ahi, w1.z, w1.w); \
            mma16816(acc[1], alo, w1.x, w1.y); \
            mma16816(acc[2], ahi, w2.x, w2.y); \
            mma16816(acc[2], ahi, w2.z, w2.w); \
            mma16816(acc[2], alo, w2.x, w2.y); \
        } while (0)

        LOADC(fb0, 0); LOADC(fb1, 1); LOADC(fb2, 2); LOADC(fb3, 3);
        LOADC(fb4, 4); LOADC(fb5, 5); LOADC(fb6, 6);

        #pragma unroll 1
        for (int c = 0; c < NCHUNK; c += 8) {
            LOADC(fb7, c + 7);  COMPUTE(fb0, c);
            LOADC(fb0, c + 8);  COMPUTE(fb1, c + 1);
            LOADC(fb1, c + 9);  COMPUTE(fb2, c + 2);
            LOADC(fb2, c + 10); COMPUTE(fb3, c + 3);
            LOADC(fb3, c + 11); COMPUTE(fb4, c + 4);
            LOADC(fb4, c + 12); COMPUTE(fb5, c + 5);
            LOADC(fb5, c + 13); COMPUTE(fb6, c + 6);
            LOADC(fb6, c + 14); COMPUTE(fb7, c + 7);
        }
        #undef LOADC
        #undef COMPUTE

        // ---- epilogue: bias, scalar emission stores, quad-shfl LSE + target ----
        #pragma unroll
        for (int rr = 0; rr < 2; rr++) {
            const long row = row0 + rr * 8 + r;
            float e[6];
            float* eo = emis + row * TT;
            #pragma unroll
            for (int nt = 0; nt < 3; nt++) {
                const int col = nt * 8 + kp * 2;
                e[nt * 2]     = acc[nt][rr * 2]     + __ldg(bias + col);
                e[nt * 2 + 1] = acc[nt][rr * 2 + 1] + __ldg(bias + col + 1);
                eo[col]     = e[nt * 2];
                eo[col + 1] = e[nt * 2 + 1];
            }
            float mx = e[0];
            #pragma unroll
            for (int q = 1; q < 6; q++) mx = fmaxf(mx, e[q]);
            mx = fmaxf(mx, __shfl_xor_sync(0xffffffffu, mx, 1));
            mx = fmaxf(mx, __shfl_xor_sync(0xffffffffu, mx, 2));
            float ex = 0.0f;
            #pragma unroll
            for (int q = 0; q < 6; q++) ex += __expf(e[q] - mx);
            const int tg = target[row];
            float sc = 0.0f;
            #pragma unroll
            for (int nt = 0; nt < 3; nt++) {
                const int col = nt * 8 + kp * 2;
                sc += (tg == col) ? e[nt * 2] : 0.0f;
                sc += (tg == col + 1) ? e[nt * 2 + 1] : 0.0f;
            }
            ex += __shfl_xor_sync(0xffffffffu, ex, 1);
            sc += __shfl_xor_sync(0xffffffffu, sc, 1);
            ex += __shfl_xor_sync(0xffffffffu, ex, 2);
            sc += __shfl_xor_sync(0xffffffffu, sc, 2);
            if (kp == 0) {
                const float lse = mx + __logf(ex);
                const int s  = (int)(row & (SS - 1));
                const int mk = getmask(mask_raw, mt_, row);
                contrib += mk ? (sc - lse) : (s == 0 ? -lse : 0.0f);
            }
        }
    }

    // ---- warp + block reduce, ticket ----
    contrib += __shfl_xor_sync(0xffffffffu, contrib, 16);
    contrib += __shfl_xor_sync(0xffffffffu, contrib, 8);
    contrib += __shfl_xor_sync(0xffffffffu, contrib, 4);
    contrib += __shfl_xor_sync(0xffffffffu, contrib, 2);
    contrib += __shfl_xor_sync(0xffffffffu, contrib, 1);
    if (lane == 0) sred[warp] = contrib;
    __syncthreads();
    if (tid == 0) {
        float part = 0.0f;
        #pragma unroll
        for (int w = 0; w < NWARP; w++) part += sred[w];
        atomicAdd(&g_loss_sum, part);
        __threadfence();
        unsigned tk = atomicAdd(&g_ticket, 1u);
        s_flag = (tk == GRID - 1);
    }
    __syncthreads();
    if (!s_flag) return;

    // ================= last block: finalize =================
    {
        int lnz = 0;
        for (int i = tid; i < TT * TT; i += NTH) {
            float v = trans[i];
            st[i] = v;
            lnz |= (v != 0.0f);
        }
        if (lnz) atomicOr(&s_nz, 1);
    }
    __syncthreads();

    if (!s_nz) {
        if (tid == 0) {
            if (has_loss) out[0] = -g_loss_sum / (float)BB;
            g_loss_sum = 0.0f;
            g_ticket = 0u;
        }
        return;
    }

    // generic nonzero-transition path (not taken for this dataset)
    {
        float wsum = 0.0f;
        float* msp = sp + warp * TT;
        for (int b = warp; b < BB; b += NWARP) {
            float sum = 0.0f;
            for (int s = lane; s < SS; s += 32) {
                const long idx = (long)b * SS + s;
                if (getmask(mask_raw, mt_, idx)) {
                    float v = emis[idx * TT + target[idx]];
                    if (s > 0) v += st[target[idx - 1] * TT + target[idx]];
                    sum += v;
                }
            }
            sum += __shfl_xor_sync(0xffffffffu, sum, 16);
            sum += __shfl_xor_sync(0xffffffffu, sum, 8);
            sum += __shfl_xor_sync(0xffffffffu, sum, 4);
            sum += __shfl_xor_sync(0xffffffffu, sum, 2);
            sum += __shfl_xor_sync(0xffffffffu, sum, 1);

            if (lane < TT) msp[lane] = emis[(long)b * SS * TT + lane];
            __syncwarp();
            for (int s = 1; s < SS; s++) {
                if (getmask(mask_raw, mt_, (long)b * SS + s)) {
                    float nv = 0.0f;
                    if (lane < TT) {
                        float mm = neg_inf();
                        #pragma unroll
                        for (int j = 0; j < TT; j++) mm = fmaxf(mm, msp[j] + st[j * TT + lane]);
                        float a = 0.0f;
                        #pragma unroll
                        for (int j = 0; j < TT; j++) a += __expf(msp[j] + st[j * TT + lane] - mm);
                        nv = emis[((long)b * SS + s) * TT + lane] + mm + __logf(a);
                    }
                    __syncwarp();
                    if (lane < TT) msp[lane] = nv;
                    __syncwarp();
                }
            }
            float e2 = (lane < TT) ? msp[lane] : neg_inf();
            float mm = e2;
            mm = fmaxf(mm, __shfl_xor_sync(0xffffffffu, mm, 16));
            mm = fmaxf(mm, __shfl_xor_sync(0xffffffffu, mm, 8));
            mm = fmaxf(mm, __shfl_xor_sync(0xffffffffu, mm, 4));
            mm = fmaxf(mm, __shfl_xor_sync(0xffffffffu, mm, 2));
            mm = fmaxf(mm, __shfl_xor_sync(0xffffffffu, mm, 1));
            float ex2 = (lane < TT) ? __expf(e2 - mm) : 0.0f;
            ex2 += __shfl_xor_sync(0xffffffffu, ex2, 16);
            ex2 += __shfl_xor_sync(0xffffffffu, ex2, 8);
            ex2 += __shfl_xor_sync(0xffffffffu, ex2, 4);
            ex2 += __shfl_xor_sync(0xffffffffu, ex2, 2);
            ex2 += __shfl_xor_sync(0xffffffffu, ex2, 1);
            if (lane == 0) wsum += sum - (mm + __logf(ex2));
        }
        if (lane == 0) atomicAdd(&s_tot, wsum);
    }
    __syncthreads();
    if (tid == 0) {
        if (has_loss) out[0] = -s_tot / (float)BB;
        g_loss_sum = 0.0f;
        g_ticket = 0u;
    }
}

// ---------------- launch ----------------
extern "C" void kernel_launch(void* const* d_in, const int* in_sizes, int n_in,
                              void* d_out, int out_size) {
    const float* feats  = (const float*)d_in[0];   // (B,S,H)
    const int*   target = (const int*)d_in[1];     // (B,S)
    const void*  mask   = d_in[2];                 // (B,S) dtype auto-detected
    const float* W      = (const float*)d_in[3];   // (T,H)
    const float* bias   = (const float*)d_in[4];   // (T,)
    const float* trans  = (const float*)d_in[5];   // (T,T)

    float* out = (float*)d_out;
    const int has_loss = (out_size == NROWS * TT + 1) ? 1 : 0;

    prep_kernel<<<24, 256>>>(W);
    crf_kernel<<<GRID, NTH>>>(feats, W, bias, target, mask, trans, out, has_loss);
}

// round 16
// speedup vs baseline: 1.5468x; 1.0770x over previous
#include <cuda_runtime.h>
#include <cuda_bf16.h>
#include <math.h>
#include <stdint.h>

#define BB 64
#define SS 512
#define HH 1024
#define TT 24
#define NROWS (BB*SS)

#define GRID 148
#define NTH 512                    // 16 warps
#define NWARP 16
#define NCHUNK 64                  // K chunks of 16
#define NTILES (NROWS/16)          // 2048 tiles of 16 rows
#define PDIST 12                   // L2 prefetch distance in chunks

// ---------------- device scratch ----------------
__device__ float    g_loss_sum;
__device__ unsigned g_ticket;
__device__ unsigned g_tile;
// pre-packed B fragments: [nt][chunk][lane] = {bh0,bh1,bl0,bl1}  (98304 B, L1-resident)
__device__ uint4    g_wfrag[3 * NCHUNK * 32];

__device__ __forceinline__ float neg_inf() { return __int_as_float(0xff800000); }

__device__ __forceinline__ uint32_t packbf(float x, float y) {
    uint32_t r; asm("cvt.rn.bf16x2.f32 %0, %1, %2;" : "=r"(r) : "f"(y), "f"(x)); return r;
}
__device__ __forceinline__ void split2f(float x, float y, uint32_t& hi, uint32_t& lo) {
    hi = packbf(x, y);
    float rx = x - __uint_as_float(hi << 16);
    float ry = y - __uint_as_float(hi & 0xFFFF0000u);
    lo = packbf(rx, ry);
}

__device__ __forceinline__ void mma16816(float* c, const uint32_t* a, uint32_t b0, uint32_t b1) {
    asm volatile("mma.sync.aligned.m16n8k16.row.col.f32.bf16.bf16.f32 "
        "{%0,%1,%2,%3}, {%4,%5,%6,%7}, {%8,%9}, {%0,%1,%2,%3};"
        : "+f"(c[0]), "+f"(c[1]), "+f"(c[2]), "+f"(c[3])
        : "r"(a[0]), "r"(a[1]), "r"(a[2]), "r"(a[3]), "r"(b0), "r"(b1));
}

__device__ __forceinline__ void pref_l2(const void* p) {
    asm volatile("prefetch.global.L2 [%0];" :: "l"(p));
}

__device__ __forceinline__ int getmask(const void* p, int mt, long i) {
    return mt == 0 ? (((const unsigned char*)p)[i] != 0)
         : mt == 1 ? (((const float*)p)[i] != 0.0f)
                   : (((const int*)p)[i] != 0);
}

// ================= prep: pack W into HMMA B-fragment layout =================
__global__ void prep_kernel(const float* __restrict__ W) {
    const int idx = blockIdx.x * blockDim.x + threadIdx.x;   // 0 .. 6143
    const int nt = idx / (NCHUNK * 32);
    const int rem = idx % (NCHUNK * 32);
    const int c = rem >> 5, lane = rem & 31;
    const int n = nt * 8 + (lane >> 2), kp = lane & 3;
    const float* wr = W + n * HH + c * 16 + kp * 4;
    uint4 f;
    uint32_t lo;
    split2f(wr[0], wr[1], f.x, lo); f.z = lo;
    split2f(wr[2], wr[3], f.y, lo); f.w = lo;
    g_wfrag[idx] = f;
}

// ================= single fused persistent kernel =================
__global__ void __launch_bounds__(NTH, 1)
crf_kernel(const float* __restrict__ feats, const float* __restrict__ W,
           const float* __restrict__ bias, const int* __restrict__ target,
           const void* __restrict__ mask_raw, const float* __restrict__ trans,
           float* __restrict__ out, int has_loss) {
    __shared__ float sred[NWARP];
    __shared__ float st[TT * TT];       // generic path only
    __shared__ float sp[NWARP * TT];    // generic path only
    __shared__ int   s_flag, s_nz;
    __shared__ float s_tot;

    const int tid = threadIdx.x, warp = tid >> 5, lane = tid & 31;
    const int r = lane >> 2, kp = lane & 3;
    float* emis = out + has_loss;       // 4B-aligned only: scalar stores

    if (tid < NWARP) sred[tid] = 0.0f;
    if (tid == 0) { s_flag = 0; s_nz = 0; s_tot = 0.0f; }
    __syncthreads();

    const unsigned u0 = *(const unsigned*)mask_raw;
    const int mt_ = (u0 == 0x01010101u) ? 0 : ((u0 == 0x3F800000u) ? 1 : 2);

    const float4* f4g = (const float4*)feats;
    const uint4* wf_base = g_wfrag + lane;
    float contrib = 0.0f;

    // ---- per-warp 16-row tile steal loop ----
    for (;;) {
        unsigned tile;
        if (lane == 0) tile = atomicAdd(&g_tile, 1u);
        tile = __shfl_sync(0xffffffffu, tile, 0);
        if (tile >= NTILES) break;
        const long row0 = (long)tile * 16;

        const long ra = (row0 + r)     * 256 + kp;   // float4 units
        const long rb = (row0 + r + 8) * 256 + kp;

        float acc[3][4];
        #pragma unroll
        for (int nt = 0; nt < 3; nt++)
            #pragma unroll
            for (int q = 0; q < 4; q++) acc[nt][q] = 0.0f;

        // warm up the L2 prefetch stream for chunks 3..PDIST-1
        #pragma unroll
        for (int p = 3; p < PDIST; p++) {
            pref_l2(f4g + ra + p * 4);
            pref_l2(f4g + rb + p * 4);
        }

        float4 fb0[2], fb1[2], fb2[2], fb3[2];

        #define LOADC(buf, c) do { \
            int _nc = (c) < NCHUNK ? (c) : (NCHUNK - 1); \
            buf[0] = __ldcs(f4g + ra + _nc * 4); \
            buf[1] = __ldcs(f4g + rb + _nc * 4); \
        } while (0)

        #define PREF(c) do { \
            if ((c) < NCHUNK) { \
                pref_l2(f4g + ra + (c) * 4); \
                pref_l2(f4g + rb + (c) * 4); \
            } \
        } while (0)

        #define COMPUTE(buf, ch) do { \
            uint4 w0 = __ldg(wf_base + (ch) * 32); \
            uint4 w1 = __ldg(wf_base + (NCHUNK * 32) + (ch) * 32); \
            uint4 w2 = __ldg(wf_base + (2 * NCHUNK * 32) + (ch) * 32); \
            uint32_t ahi[4], alo[4]; \
            split2f(buf[0].x, buf[0].y, ahi[0], alo[0]); \
            split2f(buf[1].x, buf[1].y, ahi[1], alo[1]); \
            split2f(buf[0].z, buf[0].w, ahi[2], alo[2]); \
            split2f(buf[1].z, buf[1].w, ahi[3], alo[3]); \
            mma16816(acc[0], ahi, w0.x, w0.y); \
            mma16816(acc[0], ahi, w0.z, w0.w); \
            mma16816(acc[0], alo, w0.x, w0.y); \
            mma16816(acc[1], ahi, w1.x, w1.y); \
            mma16816(acc[1], ahi, w1.z, w1.w); \
            mma16816(acc[1], alo, w1.x, w1.y); \
            mma16816(acc[2], ahi, w2.x, w2.y); \
            mma16816(acc[2], ahi, w2.z, w2.w); \
            mma16816(acc[2], alo, w2.x, w2.y); \
        } while (0)

        LOADC(fb0, 0);
        LOADC(fb1, 1);
        LOADC(fb2, 2);
        #pragma unroll 4
        for (int c = 0; c < NCHUNK; c += 4) {
            PREF(c + PDIST);
            LOADC(fb3, c + 3); COMPUTE(fb0, c);
            PREF(c + PDIST + 1);
            LOADC(fb0, c + 4); COMPUTE(fb1, c + 1);
            PREF(c + PDIST + 2);
            LOADC(fb1, c + 5); COMPUTE(fb2, c + 2);
            PREF(c + PDIST + 3);
            LOADC(fb2, c + 6); COMPUTE(fb3, c + 3);
        }
        #undef LOADC
        #undef PREF
        #undef COMPUTE

        // ---- epilogue: bias, scalar emission stores, quad-shfl LSE + target ----
        #pragma unroll
        for (int rr = 0; rr < 2; rr++) {
            const long row = row0 + rr * 8 + r;
            float e[6];
            float* eo = emis + row * TT;
            #pragma unroll
            for (int nt = 0; nt < 3; nt++) {
                const int col = nt * 8 + kp * 2;
                e[nt * 2]     = acc[nt][rr * 2]     + __ldg(bias + col);
                e[nt * 2 + 1] = acc[nt][rr * 2 + 1] + __ldg(bias + col + 1);
                eo[col]     = e[nt * 2];
                eo[col + 1] = e[nt * 2 + 1];
            }
            float mx = e[0];
            #pragma unroll
            for (int q = 1; q < 6; q++) mx = fmaxf(mx, e[q]);
            mx = fmaxf(mx, __shfl_xor_sync(0xffffffffu, mx, 1));
            mx = fmaxf(mx, __shfl_xor_sync(0xffffffffu, mx, 2));
            float ex = 0.0f;
            #pragma unroll
            for (int q = 0; q < 6; q++) ex += __expf(e[q] - mx);
            const int tg = target[row];
            float sc = 0.0f;
            #pragma unroll
            for (int nt = 0; nt < 3; nt++) {
                const int col = nt * 8 + kp * 2;
                sc += (tg == col) ? e[nt * 2] : 0.0f;
                sc += (tg == col + 1) ? e[nt * 2 + 1] : 0.0f;
            }
            ex += __shfl_xor_sync(0xffffffffu, ex, 1);
            sc += __shfl_xor_sync(0xffffffffu, sc, 1);
            ex += __shfl_xor_sync(0xffffffffu, ex, 2);
            sc += __shfl_xor_sync(0xffffffffu, sc, 2);
            if (kp == 0) {
                const float lse = mx + __logf(ex);
                const int s  = (int)(row & (SS - 1));
                const int mk = getmask(mask_raw, mt_, row);
                contrib += mk ? (sc - lse) : (s == 0 ? -lse : 0.0f);
            }
        }
    }

    // ---- warp + block reduce, ticket ----
    contrib += __shfl_xor_sync(0xffffffffu, contrib, 16);
    contrib += __shfl_xor_sync(0xffffffffu, contrib, 8);
    contrib += __shfl_xor_sync(0xffffffffu, contrib, 4);
    contrib += __shfl_xor_sync(0xffffffffu, contrib, 2);
    contrib += __shfl_xor_sync(0xffffffffu, contrib, 1);
    if (lane == 0) sred[warp] = contrib;
    __syncthreads();
    if (tid == 0) {
        float part = 0.0f;
        #pragma unroll
        for (int w = 0; w < NWARP; w++) part += sred[w];
        atomicAdd(&g_loss_sum, part);
        __threadfence();
        unsigned tk = atomicAdd(&g_ticket, 1u);
        s_flag = (tk == GRID - 1);
    }
    __syncthreads();
    if (!s_flag) return;

    // ================= last block: finalize =================
    {
        int lnz = 0;
        for (int i = tid; i < TT * TT; i += NTH) {
            float v = trans[i];
            st[i] = v;
            lnz |= (v != 0.0f);
        }
        if (lnz) atomicOr(&s_nz, 1);
    }
    __syncthreads();

    if (!s_nz) {
        if (tid == 0) {
            if (has_loss) out[0] = -g_loss_sum / (float)BB;
            g_loss_sum = 0.0f;
            g_ticket = 0u;
            g_tile = 0u;
        }
        return;
    }

    // generic nonzero-transition path (not taken for this dataset)
    {
        float wsum = 0.0f;
        float* msp = sp + warp * TT;
        for (int b = warp; b < BB; b += NWARP) {
            float sum = 0.0f;
            for (int s = lane; s < SS; s += 32) {
                const long idx = (long)b * SS + s;
                if (getmask(mask_raw, mt_, idx)) {
                    float v = emis[idx * TT + target[idx]];
                    if (s > 0) v += st[target[idx - 1] * TT + target[idx]];
                    sum += v;
                }
            }
            sum += __shfl_xor_sync(0xffffffffu, sum, 16);
            sum += __shfl_xor_sync(0xffffffffu, sum, 8);
            sum += __shfl_xor_sync(0xffffffffu, sum, 4);
            sum += __shfl_xor_sync(0xffffffffu, sum, 2);
            sum += __shfl_xor_sync(0xffffffffu, sum, 1);

            if (lane < TT) msp[lane] = emis[(long)b * SS * TT + lane];
            __syncwarp();
            for (int s = 1; s < SS; s++) {
                if (getmask(mask_raw, mt_, (long)b * SS + s)) {
                    float nv = 0.0f;
                    if (lane < TT) {
                        float mm = neg_inf();
                        #pragma unroll
                        for (int j = 0; j < TT; j++) mm = fmaxf(mm, msp[j] + st[j * TT + lane]);
                        float a = 0.0f;
                        #pragma unroll
                        for (int j = 0; j < TT; j++) a += __expf(msp[j] + st[j * TT + lane] - mm);
                        nv = emis[((long)b * SS + s) * TT + lane] + mm + __logf(a);
                    }
                    __syncwarp();
                    if (lane < TT) msp[lane] = nv;
                    __syncwarp();
                }
            }
            float e2 = (lane < TT) ? msp[lane] : neg_inf();
            float mm = e2;
            mm = fmaxf(mm, __shfl_xor_sync(0xffffffffu, mm, 16));
            mm = fmaxf(mm, __shfl_xor_sync(0xffffffffu, mm, 8));
            mm = fmaxf(mm, __shfl_xor_sync(0xffffffffu, mm, 4));
            mm = fmaxf(mm, __shfl_xor_sync(0xffffffffu, mm, 2));
            mm = fmaxf(mm, __shfl_xor_sync(0xffffffffu, mm, 1));
            float ex2 = (lane < TT) ? __expf(e2 - mm) : 0.0f;
            ex2 += __shfl_xor_sync(0xffffffffu, ex2, 16);
            ex2 += __shfl_xor_sync(0xffffffffu, ex2, 8);
            ex2 += __shfl_xor_sync(0xffffffffu, ex2, 4);
            ex2 += __shfl_xor_sync(0xffffffffu, ex2, 2);
            ex2 += __shfl_xor_sync(0xffffffffu, ex2, 1);
            if (lane == 0) wsum += sum - (mm + __logf(ex2));
        }
        if (lane == 0) atomicAdd(&s_tot, wsum);
    }
    __syncthreads();
    if (tid == 0) {
        if (has_loss) out[0] = -s_tot / (float)BB;
        g_loss_sum = 0.0f;
        g_ticket = 0u;
        g_tile = 0u;
    }
}

// ---------------- launch ----------------
extern "C" void kernel_launch(void* const* d_in, const int* in_sizes, int n_in,
                              void* d_out, int out_size) {
    const float* feats  = (const float*)d_in[0];   // (B,S,H)
    const int*   target = (const int*)d_in[1];     // (B,S)
    const void*  mask   = d_in[2];                 // (B,S) dtype auto-detected
    const float* W      = (const float*)d_in[3];   // (T,H)
    const float* bias   = (const float*)d_in[4];   // (T,)
    const float* trans  = (const float*)d_in[5];   // (T,T)

    float* out = (float*)d_out;
    const int has_loss = (out_size == NROWS * TT + 1) ? 1 : 0;

    prep_kernel<<<24, 256>>>(W);
    crf_kernel<<<GRID, NTH>>>(feats, W, bias, target, mask, trans, out, has_loss);
}